// round 4
// baseline (speedup 1.0000x reference)
#include <cuda_runtime.h>
#include <cstdint>

// Problem constants (fixed by the reference)
#define NN 50000
#define EE 800000
#define DD 64
#define GG 64
#define BN_EPS 1e-4f

typedef unsigned long long u64;

// ---------------- scratch (static __device__ allocation, allowed) -------------
__device__ float g_x[NN * DD];       // current x (post-MLP, pre-BN)
__device__ float g_s0[NN * DD];      // s ping
__device__ float g_s1[NN * DD];      // s pong
__device__ float g_aggx[NN * DD];    // GIN aggregated x (+self)
__device__ float g_aggs[NN * DD];    // GIN aggregated s (+self)
__device__ float g_sw[NN * DD];      // s @ Wg[i]
__device__ float g_dinv[NN];
__device__ int   g_deg[NN];
__device__ int   g_pos[NN];
__device__ int   g_rowptr[NN + 1];
__device__ int   g_csr[EE];
__device__ float g_bnsum[DD];
__device__ float g_bnsq[DD];
__device__ float g_mean[DD];
__device__ float g_istd[DD];
__device__ int   g_stride;           // 1 = int32 index buffers, 2 = int64 (read low words)

// ---------------- packed f32x2 helpers ---------------------------------------
__device__ __forceinline__ u64 pack2(float lo, float hi) {
    u64 r;
    asm("mov.b64 %0, {%1, %2};" : "=l"(r) : "f"(lo), "f"(hi));
    return r;
}
__device__ __forceinline__ void ffma2(u64& d, u64 a, u64 b) {
    asm("fma.rn.f32x2 %0, %1, %2, %0;" : "+l"(d) : "l"(a), "l"(b));
}
__device__ __forceinline__ float lo32(u64 v) { return __uint_as_float((unsigned)(v & 0xffffffffull)); }
__device__ __forceinline__ float hi32(u64 v) { return __uint_as_float((unsigned)(v >> 32)); }

// ---------------- dtype-layout detection --------------------------------------
// If edge_index is int64 (LE, values < 50000), odd 32-bit words of the first
// 8 elements are all zero. If int32, they're uniform random in [0, 50000).
__global__ void k_detect(const int* __restrict__ ei) {
    if (threadIdx.x == 0) {
        int nz = 0;
#pragma unroll
        for (int j = 1; j < 16; j += 2) nz += (ei[j] != 0);
        g_stride = (nz == 0) ? 2 : 1;
    }
}

// ---------------- setup kernels ----------------------------------------------
__global__ void k_zero(float* __restrict__ pooled) {
    int i = blockIdx.x * 256 + threadIdx.x;
    if (i < NN) g_deg[i] = 0;
    if (i < GG * DD) pooled[i] = 0.f;
    if (i < DD) { g_bnsum[i] = 0.f; g_bnsq[i] = 0.f; }
}

__global__ void k_hist(const int* __restrict__ ei) {
    int st = g_stride;
    int e = blockIdx.x * 256 + threadIdx.x;
    if (e < EE) {
        unsigned d = (unsigned)ei[(EE + e) * st];
        if (d < NN) atomicAdd(&g_deg[d], 1);
    }
}

// single-block exclusive scan over g_deg -> g_rowptr
__global__ void k_scan() {
    __shared__ int partial[1024];
    int tid = threadIdx.x;
    const int IPT = (NN + 1023) / 1024;  // 49
    int base = tid * IPT;
    int sum = 0;
    for (int j = 0; j < IPT; j++) {
        int idx = base + j;
        if (idx < NN) sum += g_deg[idx];
    }
    partial[tid] = sum;
    __syncthreads();
    for (int off = 1; off < 1024; off <<= 1) {
        int v = (tid >= off) ? partial[tid - off] : 0;
        __syncthreads();
        partial[tid] += v;
        __syncthreads();
    }
    int run = (tid == 0) ? 0 : partial[tid - 1];
    for (int j = 0; j < IPT; j++) {
        int idx = base + j;
        if (idx < NN) { g_rowptr[idx] = run; run += g_deg[idx]; }
    }
    if (tid == 0) g_rowptr[NN] = partial[1023];
}

__global__ void k_dinv() {
    int n = blockIdx.x * 256 + threadIdx.x;
    if (n < NN) {
        g_dinv[n] = rsqrtf((float)g_deg[n] + 1.0f);  // +1 = self loop
        g_pos[n] = g_rowptr[n];
    }
}

__global__ void k_scatter(const int* __restrict__ ei) {
    int st = g_stride;
    int e = blockIdx.x * 256 + threadIdx.x;
    if (e < EE) {
        unsigned d = (unsigned)ei[(EE + e) * st];
        unsigned srcv = (unsigned)ei[e * st];
        if (d < NN && srcv < NN) {
            int idx = atomicAdd(&g_pos[d], 1);
            g_csr[idx] = (int)srcv;
        }
    }
}

// ---------------- aggregation: warp per node ----------------------------------
// aggx = sum_{src->n} x[src] + x[n];  aggs likewise for s
// snew[n] = tanh( dinv[n]*sum dinv[src]*sw[src] + dinv[n]^2*sw[n] + bg )
__global__ void __launch_bounds__(256) k_agg(const float* __restrict__ x,
                                             const float* __restrict__ s,
                                             const float* __restrict__ bg,
                                             float* __restrict__ snew) {
    int w = (blockIdx.x * 256 + threadIdx.x) >> 5;
    int lane = threadIdx.x & 31;
    if (w >= NN) return;
    int n = w;
    int beg = g_rowptr[n], end = g_rowptr[n + 1];
    float ax0 = x[n * 64 + lane], ax1 = x[n * 64 + 32 + lane];
    float as0 = s[n * 64 + lane], as1 = s[n * 64 + 32 + lane];
    float aw0 = 0.f, aw1 = 0.f;
    for (int e = beg; e < end; ++e) {
        int src = g_csr[e];
        float wd = g_dinv[src];
        const float* xr = x + src * 64;
        const float* sr = s + src * 64;
        const float* wr = g_sw + src * 64;
        ax0 += xr[lane];      ax1 += xr[lane + 32];
        as0 += sr[lane];      as1 += sr[lane + 32];
        aw0 += wd * wr[lane]; aw1 += wd * wr[lane + 32];
    }
    g_aggx[n * 64 + lane] = ax0;      g_aggx[n * 64 + 32 + lane] = ax1;
    g_aggs[n * 64 + lane] = as0;      g_aggs[n * 64 + 32 + lane] = as1;
    float di = g_dinv[n];
    float sn0 = di * aw0 + di * di * g_sw[n * 64 + lane] + bg[lane];
    float sn1 = di * aw1 + di * di * g_sw[n * 64 + 32 + lane] + bg[lane + 32];
    snew[n * 64 + lane] = tanhf(sn0);
    snew[n * 64 + 32 + lane] = tanhf(sn1);
}

// ---------------- GEMM: g_sw = s @ Wg (K=64, C=64), packed f32x2 ---------------
__global__ void __launch_bounds__(256) k_gemm_sw(const float* __restrict__ in,
                                                 const float* __restrict__ W) {
    __shared__ float sIn[64 * 64];
    __shared__ float sW[64 * 64];
    int tid = threadIdx.x;
    int row0 = blockIdx.x * 64;
    int nrows = min(64, NN - row0);
    for (int j = tid; j < 1024; j += 256) ((float4*)sW)[j] = ((const float4*)W)[j];
    {
        int nfl4 = nrows * 16;
        const float4* i4 = (const float4*)(in + row0 * 64);
        for (int j = tid; j < 1024; j += 256)
            ((float4*)sIn)[j] = (j < nfl4) ? i4[j] : make_float4(0, 0, 0, 0);
    }
    __syncthreads();
    int r = tid >> 2, q = tid & 3, c0 = q * 16;
    u64 acc[8];
#pragma unroll
    for (int j = 0; j < 8; j++) acc[j] = 0ull;
    const float* inr = sIn + r * 64;
#pragma unroll 4
    for (int k = 0; k < 64; k++) {
        float v = inr[k];
        u64 a = pack2(v, v);
        const u64* wr = (const u64*)(sW + k * 64) + (c0 >> 1);
#pragma unroll
        for (int j = 0; j < 8; j++) ffma2(acc[j], a, wr[j]);
    }
    if (r < nrows) {
        u64* o = (u64*)(g_sw + (row0 + r) * 64 + c0);
#pragma unroll
        for (int j = 0; j < 8; j++) o[j] = acc[j];
    }
}

// ---------------- fused GIN MLP: g_x = leaky([aggx|aggs]@W1)@W2 ----------------
// dynamic smem: A = 64x128 input tile (32KB), B = weights (32KB)
__global__ void __launch_bounds__(256) k_mlp(const float* __restrict__ W1,
                                             const float* __restrict__ W2) {
    extern __shared__ float sm[];
    float* A = sm;
    float* B = sm + 8192;
    int tid = threadIdx.x;
    int row0 = blockIdx.x * 64;
    int nrows = min(64, NN - row0);
    for (int j = tid; j < 2048; j += 256) {
        int r = j >> 5, c4 = j & 31;
        float4 v = make_float4(0, 0, 0, 0);
        if (r < nrows) {
            int row = row0 + r;
            v = (c4 < 16) ? ((const float4*)(g_aggx + row * 64))[c4]
                          : ((const float4*)(g_aggs + row * 64))[c4 - 16];
        }
        ((float4*)A)[j] = v;
    }
    for (int j = tid; j < 2048; j += 256) ((float4*)B)[j] = ((const float4*)W1)[j];
    __syncthreads();

    int r = tid >> 2, q = tid & 3, c0 = q * 16;
    u64 acc[8];
#pragma unroll
    for (int j = 0; j < 8; j++) acc[j] = 0ull;
    const float* inr = A + r * 128;
#pragma unroll 4
    for (int k = 0; k < 128; k++) {
        float v = inr[k];
        u64 a = pack2(v, v);
        const u64* wr = (const u64*)(B + k * 64) + (c0 >> 1);
#pragma unroll
        for (int j = 0; j < 8; j++) ffma2(acc[j], a, wr[j]);
    }
    // leaky ReLU
    u64 mid[8];
#pragma unroll
    for (int j = 0; j < 8; j++) {
        float lo = lo32(acc[j]), hi = hi32(acc[j]);
        lo = lo > 0.f ? lo : 0.01f * lo;
        hi = hi > 0.f ? hi : 0.01f * hi;
        mid[j] = pack2(lo, hi);
    }
    __syncthreads();  // done reading A/B
    {
        u64* mrow = (u64*)(A + r * 64 + c0);
#pragma unroll
        for (int j = 0; j < 8; j++) mrow[j] = mid[j];
    }
    for (int j = tid; j < 1024; j += 256) ((float4*)B)[j] = ((const float4*)W2)[j];
    __syncthreads();

    u64 acc2[8];
#pragma unroll
    for (int j = 0; j < 8; j++) acc2[j] = 0ull;
    const float* mr = A + r * 64;
#pragma unroll 4
    for (int k = 0; k < 64; k++) {
        float v = mr[k];
        u64 a = pack2(v, v);
        const u64* wr = (const u64*)(B + k * 64) + (c0 >> 1);
#pragma unroll
        for (int j = 0; j < 8; j++) ffma2(acc2[j], a, wr[j]);
    }
    if (r < nrows) {
        u64* o = (u64*)(g_x + (row0 + r) * 64 + c0);
#pragma unroll
        for (int j = 0; j < 8; j++) o[j] = acc2[j];
    }
}

// ---------------- BatchNorm stats (last layer only) ----------------------------
__global__ void __launch_bounds__(256) k_bnstats() {
    __shared__ float ssum[64], ssq[64];
    int tid = threadIdx.x;
    if (tid < 64) { ssum[tid] = 0.f; ssq[tid] = 0.f; }
    __syncthreads();
    int c = tid & 63, rc = tid >> 6;
    float sum = 0.f, sq = 0.f;
    for (int r = blockIdx.x * 4 + rc; r < NN; r += gridDim.x * 4) {
        float v = g_x[r * 64 + c];
        sum += v;
        sq += v * v;
    }
    atomicAdd(&ssum[c], sum);
    atomicAdd(&ssq[c], sq);
    __syncthreads();
    if (tid < 64) {
        atomicAdd(&g_bnsum[tid], ssum[tid]);
        atomicAdd(&g_bnsq[tid], ssq[tid]);
    }
}

__global__ void k_bnfinal() {
    int c = threadIdx.x;
    if (c < 64) {
        float m = g_bnsum[c] * (1.0f / (float)NN);
        float var = g_bnsq[c] * (1.0f / (float)NN) - m * m;
        g_mean[c] = m;
        g_istd[c] = rsqrtf(var + BN_EPS);
    }
}

// ---------------- final: BN-apply + concat GEMM + pooled scatter ---------------
__global__ void __launch_bounds__(256) k_final(const float* __restrict__ Wh,
                                               const float* __restrict__ bh,
                                               const float* __restrict__ gamma,
                                               const float* __restrict__ beta,
                                               const int* __restrict__ batch,
                                               float* __restrict__ pooled,
                                               float* __restrict__ xlocal) {
    extern __shared__ float sm[];
    float* A = sm;         // [64][128]: BN(x) | s
    float* B = sm + 8192;  // Wh [128][64]
    __shared__ int sb[64];
    int tid = threadIdx.x;
    int row0 = blockIdx.x * 64;
    int nrows = min(64, NN - row0);

    for (int j = tid; j < 2048; j += 256) {
        int r = j >> 5, c4 = j & 31;
        float4 v = make_float4(0, 0, 0, 0);
        if (r < nrows) {
            int row = row0 + r;
            if (c4 < 16) {
                float4 xv = ((const float4*)(g_x + row * 64))[c4];
                int c = c4 * 4;
                float4 o;
                o.x = gamma[c + 0] * (xv.x - g_mean[c + 0]) * g_istd[c + 0] + beta[c + 0];
                o.y = gamma[c + 1] * (xv.y - g_mean[c + 1]) * g_istd[c + 1] + beta[c + 1];
                o.z = gamma[c + 2] * (xv.z - g_mean[c + 2]) * g_istd[c + 2] + beta[c + 2];
                o.w = gamma[c + 3] * (xv.w - g_mean[c + 3]) * g_istd[c + 3] + beta[c + 3];
                ((float4*)(xlocal + row * 64))[c4] = o;
                v = o;
            } else {
                v = ((const float4*)(g_s0 + row * 64))[c4 - 16];
            }
        }
        ((float4*)A)[j] = v;
    }
    for (int j = tid; j < 2048; j += 256) ((float4*)B)[j] = ((const float4*)Wh)[j];
    {
        int st = g_stride;
        if (tid < 64) sb[tid] = (tid < nrows) ? batch[(row0 + tid) * st] : -1;
    }
    __syncthreads();

    int r = tid >> 2, q = tid & 3, c0 = q * 16;
    u64 acc[8];
#pragma unroll
    for (int j = 0; j < 8; j++) acc[j] = pack2(bh[c0 + 2 * j], bh[c0 + 2 * j + 1]);
    const float* inr = A + r * 128;
#pragma unroll 4
    for (int k = 0; k < 128; k++) {
        float v = inr[k];
        u64 a = pack2(v, v);
        const u64* wr = (const u64*)(B + k * 64) + (c0 >> 1);
#pragma unroll
        for (int j = 0; j < 8; j++) ffma2(acc[j], a, wr[j]);
    }
    __syncthreads();  // done reading A
    {
        u64* orow = (u64*)(A + r * 64 + c0);
#pragma unroll
        for (int j = 0; j < 8; j++) orow[j] = acc[j];
    }
    __syncthreads();
    // segmented pool: batch is sorted -> few distinct graphs per block
    {
        int c = tid & 63, sg = tid >> 6;
        float run = 0.f;
        int cur = -1;
        for (int rr = sg * 16; rr < sg * 16 + 16; ++rr) {
            int b = sb[rr];
            if (b != cur) {
                if (cur >= 0 && cur < GG) atomicAdd(&pooled[cur * 64 + c], run);
                run = 0.f;
                cur = b;
            }
            if (b >= 0) run += A[rr * 64 + c];
        }
        if (cur >= 0 && cur < GG) atomicAdd(&pooled[cur * 64 + c], run);
    }
}

// ---------------- launch -------------------------------------------------------
extern "C" void kernel_launch(void* const* d_in, const int* in_sizes, int n_in,
                              void* d_out, int out_size) {
    const float* x     = (const float*)d_in[0];
    const float* s     = (const float*)d_in[1];
    const float* W1    = (const float*)d_in[2];
    const float* W2    = (const float*)d_in[3];
    const float* gamma = (const float*)d_in[4];
    const float* beta  = (const float*)d_in[5];
    const float* Wg    = (const float*)d_in[6];
    const float* bg    = (const float*)d_in[7];
    const float* Wh    = (const float*)d_in[8];
    const float* bh    = (const float*)d_in[9];
    const int*   ei    = (const int*)d_in[10];
    const int*   batch = (const int*)d_in[11];

    float* outp   = (float*)d_out;
    float* pooled = outp;             // [G, D]
    float* xlocal = outp + GG * DD;   // [N, D]

    cudaFuncSetAttribute(k_mlp, cudaFuncAttributeMaxDynamicSharedMemorySize, 65536);
    cudaFuncSetAttribute(k_final, cudaFuncAttributeMaxDynamicSharedMemorySize, 65536);

    float *s0p, *s1p;
    cudaGetSymbolAddress((void**)&s0p, g_s0);
    cudaGetSymbolAddress((void**)&s1p, g_s1);
    float* gxp;
    cudaGetSymbolAddress((void**)&gxp, g_x);

    const int GB = (NN + 63) / 64;          // 782
    const int EB = (EE + 255) / 256;        // 3125
    const int NB = (NN + 255) / 256;        // 196

    k_detect<<<1, 32>>>(ei);
    k_zero<<<NB, 256>>>(pooled);
    k_hist<<<EB, 256>>>(ei);
    k_scan<<<1, 1024>>>();
    k_dinv<<<NB, 256>>>();
    k_scatter<<<EB, 256>>>(ei);

    const float* sin[3]  = {s, s0p, s1p};
    float*       sout[3] = {s0p, s1p, s0p};
    const float* xin = x;
    for (int i = 0; i < 3; i++) {
        k_gemm_sw<<<GB, 256>>>(sin[i], Wg + i * DD * DD);
        k_agg<<<(NN * 32 + 255) / 256, 256>>>(xin, sin[i], bg + i * DD, sout[i]);
        k_mlp<<<GB, 256, 65536>>>(W1 + i * 2 * DD * DD, W2 + i * DD * DD);
        xin = gxp;
    }
    k_bnstats<<<256, 256>>>();
    k_bnfinal<<<1, 64>>>();
    k_final<<<GB, 256, 65536>>>(Wh, bh, gamma + 2 * DD, beta + 2 * DD, batch,
                                pooled, xlocal);
}

// round 16
// speedup vs baseline: 1.0927x; 1.0927x over previous
#include <cuda_runtime.h>
#include <cstdint>

#define NN 50000
#define EE 800000
#define DD 64
#define GG 64
#define BN_EPS 1e-4f

typedef unsigned long long u64;

#define NBLK 98          // rowptr scan blocks of 512
// ---------------- scratch ------------------------------------------------------
__device__ float g_xs[NN * 128];     // interleaved [x(64) | s(64)] per node
__device__ float g_agg[NN * 128];    // [aggx | aggs] per node
__device__ float g_aggw[NN * 64];    // GCN pre-GEMM vector per node
__device__ float g_dinv[NN];
__device__ int   g_deg[NN];
__device__ int   g_pos[NN];
__device__ int   g_rowptr[NN + 1];
__device__ int   g_csr[EE];
__device__ int   g_bsum[NBLK];
__device__ int   g_boff[NBLK];
__device__ float g_bnsum[DD];
__device__ float g_bnsq[DD];
__device__ float g_mean[DD];
__device__ float g_istd[DD];
__device__ int   g_stride;           // 1 = int32 index buffers, 2 = int64 low words

// ---------------- packed f32x2 helpers -----------------------------------------
__device__ __forceinline__ u64 pack2(float lo, float hi) {
    u64 r;
    asm("mov.b64 %0, {%1, %2};" : "=l"(r) : "f"(lo), "f"(hi));
    return r;
}
__device__ __forceinline__ void ffma2(u64& d, u64 a, u64 b) {
    asm("fma.rn.f32x2 %0, %1, %2, %0;" : "+l"(d) : "l"(a), "l"(b));
}
__device__ __forceinline__ float lo32(u64 v) { return __uint_as_float((unsigned)(v & 0xffffffffull)); }
__device__ __forceinline__ float hi32(u64 v) { return __uint_as_float((unsigned)(v >> 32)); }

// ---------------- dtype-layout detection ---------------------------------------
__global__ void k_detect(const int* __restrict__ ei) {
    if (threadIdx.x == 0) {
        int nz = 0;
#pragma unroll
        for (int j = 1; j < 16; j += 2) nz += (ei[j] != 0);
        g_stride = (nz == 0) ? 2 : 1;
    }
}

// ---------------- setup --------------------------------------------------------
__global__ void k_zero(float* __restrict__ pooled) {
    int i = blockIdx.x * 256 + threadIdx.x;
    if (i < NN) g_deg[i] = 0;
    if (i < GG * DD) pooled[i] = 0.f;
    if (i < DD) { g_bnsum[i] = 0.f; g_bnsq[i] = 0.f; }
}

// pack inputs into interleaved layout
__global__ void k_pack(const float* __restrict__ x, const float* __restrict__ s) {
    int j = blockIdx.x * 256 + threadIdx.x;          // float4 index, NN*32 total
    if (j >= NN * 32) return;
    int n = j >> 5, k = j & 31;
    float4 v = (k < 16) ? ((const float4*)(x + n * 64))[k]
                        : ((const float4*)(s + n * 64))[k - 16];
    ((float4*)(g_xs + n * 128))[k] = v;
}

__global__ void k_hist(const int* __restrict__ ei) {
    int st = g_stride;
    int e = blockIdx.x * 256 + threadIdx.x;
    if (e < EE) {
        unsigned d = (unsigned)ei[(EE + e) * st];
        if (d < NN) atomicAdd(&g_deg[d], 1);
    }
}

__global__ void k_bsum() {                           // grid NBLK, block 512
    __shared__ int sd[512];
    int tid = threadIdx.x, idx = blockIdx.x * 512 + tid;
    sd[tid] = (idx < NN) ? g_deg[idx] : 0;
    __syncthreads();
    for (int off = 256; off > 0; off >>= 1) {
        if (tid < off) sd[tid] += sd[tid + off];
        __syncthreads();
    }
    if (tid == 0) g_bsum[blockIdx.x] = sd[0];
}

__global__ void k_bscan() {                          // 1 block, 128 threads
    __shared__ int sd[128];
    int tid = threadIdx.x;
    int v = (tid < NBLK) ? g_bsum[tid] : 0;
    sd[tid] = v;
    __syncthreads();
    for (int off = 1; off < 128; off <<= 1) {
        int t = (tid >= off) ? sd[tid - off] : 0;
        __syncthreads();
        sd[tid] += t;
        __syncthreads();
    }
    if (tid < NBLK) g_boff[tid] = sd[tid] - v;       // exclusive
}

__global__ void k_rowptr() {                         // grid NBLK, block 512
    __shared__ int sd[512];
    int tid = threadIdx.x, idx = blockIdx.x * 512 + tid;
    int v = (idx < NN) ? g_deg[idx] : 0;
    sd[tid] = v;
    __syncthreads();
    for (int off = 1; off < 512; off <<= 1) {
        int t = (tid >= off) ? sd[tid - off] : 0;
        __syncthreads();
        sd[tid] += t;
        __syncthreads();
    }
    if (idx < NN) {
        int rp = g_boff[blockIdx.x] + sd[tid] - v;
        g_rowptr[idx] = rp;
        g_pos[idx] = rp;
        g_dinv[idx] = rsqrtf((float)v + 1.0f);       // +1 self loop
        if (idx == NN - 1) g_rowptr[NN] = rp + v;
    }
}

__global__ void k_scatter(const int* __restrict__ ei) {
    int st = g_stride;
    int e = blockIdx.x * 256 + threadIdx.x;
    if (e < EE) {
        unsigned d = (unsigned)ei[(EE + e) * st];
        unsigned srcv = (unsigned)ei[e * st];
        if (d < NN && srcv < NN) {
            int idx = atomicAdd(&g_pos[d], 1);
            g_csr[idx] = (int)srcv;
        }
    }
}

// ---------------- aggregation: warp per node, one LDG.128 per lane per edge ----
// g_agg[n] = [ x[n]+Σx[src] | s[n]+Σs[src] ]
// g_aggw[n] = di*Σ dinv[src]*s[src] + di^2*s[n]
__global__ void __launch_bounds__(256) k_agg() {
    int w = (blockIdx.x * 256 + threadIdx.x) >> 5;
    int lane = threadIdx.x & 31;
    if (w >= NN) return;
    int n = w;
    int beg = g_rowptr[n], end = g_rowptr[n + 1];
    float4 self = ((const float4*)(g_xs + n * 128))[lane];
    float4 acc = self;                                // includes self term
    float4 accw = make_float4(0.f, 0.f, 0.f, 0.f);
#pragma unroll 4
    for (int e = beg; e < end; ++e) {
        int src = g_csr[e];
        float wd = g_dinv[src];
        float4 v = ((const float4*)(g_xs + src * 128))[lane];
        acc.x += v.x; acc.y += v.y; acc.z += v.z; acc.w += v.w;
        accw.x += wd * v.x; accw.y += wd * v.y;
        accw.z += wd * v.z; accw.w += wd * v.w;
    }
    ((float4*)(g_agg + n * 128))[lane] = acc;
    if (lane >= 16) {                                 // s-half lanes
        float di = g_dinv[n];
        float di2 = di * di;
        float4 o;
        o.x = di * accw.x + di2 * self.x;
        o.y = di * accw.y + di2 * self.y;
        o.z = di * accw.z + di2 * self.z;
        o.w = di * accw.w + di2 * self.w;
        ((float4*)(g_aggw + n * 64))[lane - 16] = o;
    }
}

// ---------------- fused per-layer GEMMs ----------------------------------------
// x    = leaky([aggx|aggs] @ W1) @ W2          -> g_xs[:, 0:64]
// snew = tanh(aggw @ Wg + bg)                  -> g_xs[:, 64:128]
// dyn smem: A[8192] floats (32KB), B[8192] floats (32KB)
__global__ void __launch_bounds__(256) k_mlp(const float* __restrict__ W1,
                                             const float* __restrict__ W2,
                                             const float* __restrict__ Wg,
                                             const float* __restrict__ bg) {
    extern __shared__ float sm[];
    float* A = sm;
    float* B = sm + 8192;
    int tid = threadIdx.x;
    int row0 = blockIdx.x * 64;
    int nrows = min(64, NN - row0);

    // phase 1 loads: A = agg tile [64x128], B = W1 [128x64]
    {
        int nfl4 = nrows * 32;
        const float4* a4 = (const float4*)(g_agg + row0 * 128);
        for (int j = tid; j < 2048; j += 256)
            ((float4*)A)[j] = (j < nfl4) ? a4[j] : make_float4(0, 0, 0, 0);
        for (int j = tid; j < 2048; j += 256) ((float4*)B)[j] = ((const float4*)W1)[j];
    }
    __syncthreads();

    int r = tid >> 2, q = tid & 3, c0 = q * 16;
    // GEMM1: mid = A @ W1, leaky
    u64 acc[8];
#pragma unroll
    for (int j = 0; j < 8; j++) acc[j] = 0ull;
    {
        const float* inr = A + r * 128;
#pragma unroll 4
        for (int k = 0; k < 128; k++) {
            float v = inr[k];
            u64 a = pack2(v, v);
            const u64* wr = (const u64*)(B + k * 64) + (c0 >> 1);
#pragma unroll
            for (int j = 0; j < 8; j++) ffma2(acc[j], a, wr[j]);
        }
    }
    u64 mid[8];
#pragma unroll
    for (int j = 0; j < 8; j++) {
        float lo = lo32(acc[j]), hi = hi32(acc[j]);
        lo = lo > 0.f ? lo : 0.01f * lo;
        hi = hi > 0.f ? hi : 0.01f * hi;
        mid[j] = pack2(lo, hi);
    }
    __syncthreads();   // all reads of A/B done

    // phase 2 loads: mid -> A[0:4096], aggw tile -> A[4096:8192],
    //                W2 -> B[0:4096],  Wg -> B[4096:8192]
    {
        u64* mrow = (u64*)(A + r * 64 + c0);
#pragma unroll
        for (int j = 0; j < 8; j++) mrow[j] = mid[j];
        int nfl4 = nrows * 16;
        const float4* w4 = (const float4*)(g_aggw + row0 * 64);
        float4* A2 = (float4*)(A + 4096);
        for (int j = tid; j < 1024; j += 256)
            A2[j] = (j < nfl4) ? w4[j] : make_float4(0, 0, 0, 0);
        for (int j = tid; j < 1024; j += 256) {
            ((float4*)B)[j] = ((const float4*)W2)[j];
            ((float4*)(B + 4096))[j] = ((const float4*)Wg)[j];
        }
    }
    __syncthreads();

    // GEMM2: x = mid @ W2
    u64 acc2[8];
#pragma unroll
    for (int j = 0; j < 8; j++) acc2[j] = 0ull;
    {
        const float* mr = A + r * 64;
#pragma unroll 4
        for (int k = 0; k < 64; k++) {
            float v = mr[k];
            u64 a = pack2(v, v);
            const u64* wr = (const u64*)(B + k * 64) + (c0 >> 1);
#pragma unroll
            for (int j = 0; j < 8; j++) ffma2(acc2[j], a, wr[j]);
        }
    }
    // GEMM3: snew = tanh(aggw @ Wg + bg)
    u64 acc3[8];
#pragma unroll
    for (int j = 0; j < 8; j++) acc3[j] = pack2(bg[c0 + 2 * j], bg[c0 + 2 * j + 1]);
    {
        const float* ar = A + 4096 + r * 64;
        const float* B2 = B + 4096;
#pragma unroll 4
        for (int k = 0; k < 64; k++) {
            float v = ar[k];
            u64 a = pack2(v, v);
            const u64* wr = (const u64*)(B2 + k * 64) + (c0 >> 1);
#pragma unroll
            for (int j = 0; j < 8; j++) ffma2(acc3[j], a, wr[j]);
        }
    }
    if (r < nrows) {
        float* orow = g_xs + (row0 + r) * 128;
        u64* ox = (u64*)(orow + c0);
#pragma unroll
        for (int j = 0; j < 8; j++) ox[j] = acc2[j];
        float* os = orow + 64 + c0;
#pragma unroll
        for (int j = 0; j < 8; j++) {
            os[2 * j] = tanhf(lo32(acc3[j]));
            os[2 * j + 1] = tanhf(hi32(acc3[j]));
        }
    }
}

// ---------------- BatchNorm stats (last layer only) ----------------------------
__global__ void __launch_bounds__(256) k_bnstats() {
    __shared__ float ssum[64], ssq[64];
    int tid = threadIdx.x;
    if (tid < 64) { ssum[tid] = 0.f; ssq[tid] = 0.f; }
    __syncthreads();
    int c = tid & 63, rc = tid >> 6;
    float sum = 0.f, sq = 0.f;
    for (int r = blockIdx.x * 4 + rc; r < NN; r += gridDim.x * 4) {
        float v = g_xs[r * 128 + c];
        sum += v;
        sq += v * v;
    }
    atomicAdd(&ssum[c], sum);
    atomicAdd(&ssq[c], sq);
    __syncthreads();
    if (tid < 64) {
        atomicAdd(&g_bnsum[tid], ssum[tid]);
        atomicAdd(&g_bnsq[tid], ssq[tid]);
    }
}

__global__ void k_bnfinal() {
    int c = threadIdx.x;
    if (c < 64) {
        float m = g_bnsum[c] * (1.0f / (float)NN);
        float var = g_bnsq[c] * (1.0f / (float)NN) - m * m;
        g_mean[c] = m;
        g_istd[c] = rsqrtf(var + BN_EPS);
    }
}

// ---------------- final: BN-apply + concat GEMM + pooled scatter ---------------
__global__ void __launch_bounds__(256) k_final(const float* __restrict__ Wh,
                                               const float* __restrict__ bh,
                                               const float* __restrict__ gamma,
                                               const float* __restrict__ beta,
                                               const int* __restrict__ batch,
                                               float* __restrict__ pooled,
                                               float* __restrict__ xlocal) {
    extern __shared__ float sm[];
    float* A = sm;         // [64][128]: BN(x) | s
    float* B = sm + 8192;  // Wh [128][64]
    __shared__ int sb[64];
    int tid = threadIdx.x;
    int row0 = blockIdx.x * 64;
    int nrows = min(64, NN - row0);

    for (int j = tid; j < 2048; j += 256) {
        int r = j >> 5, c4 = j & 31;
        float4 v = make_float4(0, 0, 0, 0);
        if (r < nrows) {
            int row = row0 + r;
            float4 xv = ((const float4*)(g_xs + row * 128))[c4];
            if (c4 < 16) {
                int c = c4 * 4;
                float4 o;
                o.x = gamma[c + 0] * (xv.x - g_mean[c + 0]) * g_istd[c + 0] + beta[c + 0];
                o.y = gamma[c + 1] * (xv.y - g_mean[c + 1]) * g_istd[c + 1] + beta[c + 1];
                o.z = gamma[c + 2] * (xv.z - g_mean[c + 2]) * g_istd[c + 2] + beta[c + 2];
                o.w = gamma[c + 3] * (xv.w - g_mean[c + 3]) * g_istd[c + 3] + beta[c + 3];
                ((float4*)(xlocal + row * 64))[c4] = o;
                v = o;
            } else {
                v = xv;
            }
        }
        ((float4*)A)[j] = v;
    }
    for (int j = tid; j < 2048; j += 256) ((float4*)B)[j] = ((const float4*)Wh)[j];
    {
        int st = g_stride;
        if (tid < 64) sb[tid] = (tid < nrows) ? batch[(row0 + tid) * st] : -1;
    }
    __syncthreads();

    int r = tid >> 2, q = tid & 3, c0 = q * 16;
    u64 acc[8];
#pragma unroll
    for (int j = 0; j < 8; j++) acc[j] = pack2(bh[c0 + 2 * j], bh[c0 + 2 * j + 1]);
    const float* inr = A + r * 128;
#pragma unroll 4
    for (int k = 0; k < 128; k++) {
        float v = inr[k];
        u64 a = pack2(v, v);
        const u64* wr = (const u64*)(B + k * 64) + (c0 >> 1);
#pragma unroll
        for (int j = 0; j < 8; j++) ffma2(acc[j], a, wr[j]);
    }
    __syncthreads();   // done reading A
    {
        u64* orow = (u64*)(A + r * 64 + c0);
#pragma unroll
        for (int j = 0; j < 8; j++) orow[j] = acc[j];
    }
    __syncthreads();
    // segmented pool: batch is sorted -> few distinct graphs per block
    {
        int c = tid & 63, sg = tid >> 6;
        float run = 0.f;
        int cur = -1;
        for (int rr = sg * 16; rr < sg * 16 + 16; ++rr) {
            int b = sb[rr];
            if (b != cur) {
                if (cur >= 0 && cur < GG) atomicAdd(&pooled[cur * 64 + c], run);
                run = 0.f;
                cur = b;
            }
            if (b >= 0) run += A[rr * 64 + c];
        }
        if (cur >= 0 && cur < GG) atomicAdd(&pooled[cur * 64 + c], run);
    }
}

// ---------------- launch -------------------------------------------------------
extern "C" void kernel_launch(void* const* d_in, const int* in_sizes, int n_in,
                              void* d_out, int out_size) {
    const float* x     = (const float*)d_in[0];
    const float* s     = (const float*)d_in[1];
    const float* W1    = (const float*)d_in[2];
    const float* W2    = (const float*)d_in[3];
    const float* gamma = (const float*)d_in[4];
    const float* beta  = (const float*)d_in[5];
    const float* Wg    = (const float*)d_in[6];
    const float* bg    = (const float*)d_in[7];
    const float* Wh    = (const float*)d_in[8];
    const float* bh    = (const float*)d_in[9];
    const int*   ei    = (const int*)d_in[10];
    const int*   batch = (const int*)d_in[11];

    float* outp   = (float*)d_out;
    float* pooled = outp;             // [G, D]
    float* xlocal = outp + GG * DD;   // [N, D]

    cudaFuncSetAttribute(k_mlp, cudaFuncAttributeMaxDynamicSharedMemorySize, 65536);
    cudaFuncSetAttribute(k_final, cudaFuncAttributeMaxDynamicSharedMemorySize, 65536);

    const int GB = (NN + 63) / 64;          // 782
    const int EB = (EE + 255) / 256;        // 3125
    const int NB = (NN + 255) / 256;        // 196
    const int PB = (NN * 32 + 255) / 256;   // pack blocks
    const int AB = (NN * 32 + 255) / 256;   // agg blocks (warp per node)

    k_detect<<<1, 32>>>(ei);
    k_zero<<<NB, 256>>>(pooled);
    k_pack<<<PB, 256>>>(x, s);
    k_hist<<<EB, 256>>>(ei);
    k_bsum<<<NBLK, 512>>>();
    k_bscan<<<1, 128>>>();
    k_rowptr<<<NBLK, 512>>>();
    k_scatter<<<EB, 256>>>(ei);

    for (int i = 0; i < 3; i++) {
        k_agg<<<AB, 256>>>();
        k_mlp<<<GB, 256, 65536>>>(W1 + i * 2 * DD * DD, W2 + i * DD * DD,
                                  Wg + i * DD * DD, bg + i * DD);
    }
    k_bnstats<<<256, 256>>>();
    k_bnfinal<<<1, 64>>>();
    k_final<<<GB, 256, 65536>>>(Wh, bh, gamma + 2 * DD, beta + 2 * DD, batch,
                                pooled, xlocal);
}